// round 5
// baseline (speedup 1.0000x reference)
#include <cuda_runtime.h>

#define CI     256
#define CO_ALL 256
#define HH     128
#define WW     128
#define NB     16
#define KC     8
#define NCHUNK (CI / KC)

// Binarized weights, layout [c][k][co_global]  (co_global = branch*64 + co_local)
__device__ float g_wsf[CI * 5 * CO_ALL];

// Row-delta -> smem row index map (delta+4 -> idx), rows stored: {-4,-2,-1,0,1,2,4}
__device__ const int g_rmap[9] = {0, -1, 1, 2, 3, 4, 5, -1, 6};
__device__ const int g_drow[7] = {-4, -2, -1, 0, 1, 2, 4};

__global__ void binarize_kernel(const float* __restrict__ w1, const float* __restrict__ w2,
                                const float* __restrict__ w3, const float* __restrict__ w4) {
    int idx = blockIdx.x * blockDim.x + threadIdx.x;
    const int total = 4 * 64 * CI * 5;
    if (idx >= total) return;
    int k   = idx % 5;
    int c   = (idx / 5) % CI;
    int col = (idx / (5 * CI)) % 64;
    int br  = idx / (5 * CI * 64);
    const float* wp = (br == 0) ? w1 : (br == 1) ? w2 : (br == 2) ? w3 : w4;
    // shapes (64,256,1,5) and (64,256,5,1) both flatten to col*1280 + c*5 + k
    float v = wp[(col * CI + c) * 5 + k];
    g_wsf[(c * 5 + k) * CO_ALL + br * 64 + col] = (v < 0.f) ? -1.f : 1.f;
}

__device__ __forceinline__ unsigned long long pk2(float lo, float hi) {
    unsigned long long r;
    asm("mov.b64 %0, {%1,%2};" : "=l"(r) : "f"(lo), "f"(hi));
    return r;
}
__device__ __forceinline__ void upk2(unsigned long long v, float& lo, float& hi) {
    asm("mov.b64 {%0,%1}, %2;" : "=f"(lo), "=f"(hi) : "l"(v));
}
// Packed dual FP32 FMA (Blackwell f32x2 pipe, 2 MACs / issue)
__device__ __forceinline__ void ffma2(unsigned long long& d, unsigned long long a,
                                      unsigned long long b) {
    asm("fma.rn.f32x2 %0, %1, %2, %0;" : "+l"(d) : "l"(a), "l"(b));
}

__global__ __launch_bounds__(256, 1) void mrb_main(
    const float* __restrict__ x,
    const float* __restrict__ b1, const float* __restrict__ b2,
    const float* __restrict__ b3, const float* __restrict__ b4,
    float* __restrict__ out) {
    __shared__ float xs[7][KC][136];  // 7 rows x KC channels x (128 + 8 halo)

    const int n   = blockIdx.y;
    const int h   = blockIdx.x;
    const int tid = threadIdx.x;
    const int warp = tid >> 5;
    const int lane = tid & 31;

    // Branch-uniform warps: 2 warps per branch.
    const int br     = warp >> 1;                           // 0..3
    const int co_col = (br << 3) + (lane & 7);              // 0..31
    const int wrow   = ((warp & 1) << 2) + (lane >> 3);     // 0..7
    const int co0    = co_col << 3;                         // global co base (8 co per thread)
    const int w0     = wrow << 4;                           // 16 w per thread
    const int co_l0  = (lane & 7) << 3;                     // local co within branch

    unsigned long long acc[8][8];
#pragma unroll
    for (int i = 0; i < 8; i++)
#pragma unroll
        for (int j = 0; j < 8; j++) acc[i][j] = 0ULL;

    const float* xn = x + (size_t)n * CI * HH * WW;

    for (int cb = 0; cb < NCHUNK; cb++) {
        __syncthreads();
        // Stage 7 rows x KC channels x 136 w into smem (zero-filled OOB = SAME padding)
        for (int idx = tid; idx < 7 * KC * 136; idx += 256) {
            int wv = idx % 136;
            int cc = (idx / 136) % KC;
            int r  = idx / (136 * KC);
            int hh = h + g_drow[r];
            int ww = wv - 4;
            float v = 0.f;
            if ((unsigned)hh < HH && (unsigned)ww < WW)
                v = xn[(size_t)(cb * KC + cc) * HH * WW + hh * WW + ww];
            xs[r][cc][wv] = v;
        }
        __syncthreads();

#pragma unroll
        for (int cc = 0; cc < KC; cc++) {
            const int c = cb * KC + cc;
#pragma unroll
            for (int k = 0; k < 5; k++) {
                // tap geometry (uniform per warp)
                int dw = (br <= 1) ? ((k - 2) << br) : 0;                 // horizontal shift
                int dh = (br >= 2) ? ((k - 2) << (br - 2)) : 0;           // vertical shift
                int ri = g_rmap[dh + 4];

                const float* xr = &xs[ri][cc][4 + dw + w0];
                float xv[16];
#pragma unroll
                for (int j = 0; j < 16; j++) xv[j] = xr[j];
                unsigned long long x2[8];
#pragma unroll
                for (int j = 0; j < 8; j++) x2[j] = pk2(xv[2 * j], xv[2 * j + 1]);

                const float4* wp = (const float4*)&g_wsf[(c * 5 + k) * CO_ALL + co0];
                float4 wa = wp[0], wb = wp[1];
                float s[8] = {wa.x, wa.y, wa.z, wa.w, wb.x, wb.y, wb.z, wb.w};

#pragma unroll
                for (int i = 0; i < 8; i++) {
                    unsigned long long s2 = pk2(s[i], s[i]);
#pragma unroll
                    for (int j = 0; j < 8; j++) ffma2(acc[i][j], s2, x2[j]);
                }
            }
        }
    }

    // Epilogue: add bias, store 8 co x 16 w per thread
    const float* bp = (br == 0) ? b1 : (br == 1) ? b2 : (br == 2) ? b3 : b4;
    float* op = out + (((size_t)n * CO_ALL + co0) * HH + h) * WW + w0;
#pragma unroll
    for (int i = 0; i < 8; i++) {
        float bi = bp[co_l0 + i];
        float4 o[4];
#pragma unroll
        for (int j = 0; j < 8; j++) {
            float lo, hi;
            upk2(acc[i][j], lo, hi);
            ((float2*)o)[j] = make_float2(lo + bi, hi + bi);
        }
        float4* dst = (float4*)(op + (size_t)i * HH * WW);
#pragma unroll
        for (int q = 0; q < 4; q++) dst[q] = o[q];
    }
}

extern "C" void kernel_launch(void* const* d_in, const int* in_sizes, int n_in,
                              void* d_out, int out_size) {
    const float* x  = (const float*)d_in[0];
    const float* w1 = (const float*)d_in[1];
    const float* b1 = (const float*)d_in[2];
    const float* w2 = (const float*)d_in[3];
    const float* b2 = (const float*)d_in[4];
    const float* w3 = (const float*)d_in[5];
    const float* b3 = (const float*)d_in[6];
    const float* w4 = (const float*)d_in[7];
    const float* b4 = (const float*)d_in[8];

    binarize_kernel<<<(4 * 64 * CI * 5 + 255) / 256, 256>>>(w1, w2, w3, w4);

    dim3 grid(HH, NB);
    mrb_main<<<grid, 256>>>(x, b1, b2, b3, b4, (float*)d_out);
}

// round 9
// speedup vs baseline: 5.1026x; 5.1026x over previous
#include <cuda_runtime.h>
#include <cuda_fp16.h>
#include <cstdint>

#define CI 256
#define HH 128
#define WW 128
#define NB 16
#define HW (HH*WW)
#define ASTR 72   // smem row stride in halves (144B: ldmatrix conflict-free)

// Binarized fp16 weights, layout [br][k][c][co]  (co contiguous, 64 per row)
__device__ __align__(16) __half g_wh[4 * 5 * 256 * 64];

__global__ void binarize_kernel(const float* __restrict__ w1, const float* __restrict__ w2,
                                const float* __restrict__ w3, const float* __restrict__ w4) {
    int idx = blockIdx.x * blockDim.x + threadIdx.x;
    if (idx >= 4 * 5 * 256 * 64) return;
    int co = idx & 63;
    int c  = (idx >> 6) & 255;
    int kk = idx >> 14;          // br*5 + k
    int k  = kk % 5;
    int br = kk / 5;
    const float* wp = (br == 0) ? w1 : (br == 1) ? w2 : (br == 2) ? w3 : w4;
    float v = wp[(co * CI + c) * 5 + k];
    g_wh[idx] = __float2half((v < 0.f) ? -1.f : 1.f);
}

__device__ __forceinline__ uint32_t smem_u32(const void* p) {
    return (uint32_t)__cvta_generic_to_shared(p);
}
__device__ __forceinline__ void ldsm_x4(uint32_t& r0, uint32_t& r1, uint32_t& r2, uint32_t& r3,
                                        uint32_t a) {
    asm volatile("ldmatrix.sync.aligned.m8n8.x4.shared.b16 {%0,%1,%2,%3}, [%4];"
                 : "=r"(r0), "=r"(r1), "=r"(r2), "=r"(r3) : "r"(a));
}
__device__ __forceinline__ void ldsm_x4t(uint32_t& r0, uint32_t& r1, uint32_t& r2, uint32_t& r3,
                                         uint32_t a) {
    asm volatile("ldmatrix.sync.aligned.m8n8.x4.trans.shared.b16 {%0,%1,%2,%3}, [%4];"
                 : "=r"(r0), "=r"(r1), "=r"(r2), "=r"(r3) : "r"(a));
}
__device__ __forceinline__ void mma16816(float* c, const uint32_t* a, uint32_t b0, uint32_t b1) {
    asm volatile(
        "mma.sync.aligned.m16n8k16.row.col.f32.f16.f16.f32 "
        "{%0,%1,%2,%3}, {%4,%5,%6,%7}, {%8,%9}, {%0,%1,%2,%3};"
        : "+f"(c[0]), "+f"(c[1]), "+f"(c[2]), "+f"(c[3])
        : "r"(a[0]), "r"(a[1]), "r"(a[2]), "r"(a[3]), "r"(b0), "r"(b1));
}

// ---------- main: one CTA = (branch, n, h); GEMM 128x64 x K1280 via HMMA ----------
__global__ __launch_bounds__(256) void mrb_mma(
    const float* __restrict__ x,
    const float* __restrict__ b1, const float* __restrict__ b2,
    const float* __restrict__ b3, const float* __restrict__ b4,
    float* __restrict__ out) {

    __shared__ __align__(16) __half sA[128 * ASTR];  // A: [w][c]
    __shared__ __align__(16) __half sB[64 * ASTR];   // B: [c][co]

    const int br = blockIdx.x;
    const int h  = blockIdx.y;
    const int n  = blockIdx.z;
    const int tid = threadIdx.x, wid = tid >> 5, lane = tid & 31;

    const int m0 = (wid & 3) * 32;   // w-tile base
    const int n0 = (wid >> 2) * 32;  // co-tile base

    // ldmatrix per-lane address offsets (same pattern for A rows and B k-rows)
    const int rOff = (lane & 7) + (((lane >> 3) & 1) << 3);  // +{0,8}
    const int cOff = (lane >> 4) << 3;                       // +{0,8}

    const uint32_t aB = smem_u32(sA);
    const uint32_t bB = smem_u32(sB);

    float acc[2][4][4];
#pragma unroll
    for (int mi = 0; mi < 2; mi++)
#pragma unroll
        for (int ni = 0; ni < 4; ni++)
#pragma unroll
            for (int r = 0; r < 4; r++) acc[mi][ni][r] = 0.f;

    const float* xn = x + (size_t)n * CI * HW;
    const int w  = tid & 127;
    const int ch = tid >> 7;   // which 32-channel half of the 64-chunk

    for (int cc = 0; cc < 4; cc++) {
#pragma unroll 1
        for (int k = 0; k < 5; k++) {
            __syncthreads();
            // ---- B tile: 64 c-rows x 64 co, straight copy from prepass ----
            {
                int cl = tid >> 2, q = tid & 3;
                const uint4* src = (const uint4*)(g_wh +
                    (((size_t)(br * 5 + k) * 256) + cc * 64 + cl) * 64 + q * 16);
                uint4* dst = (uint4*)(sB + cl * ASTR + q * 16);
                dst[0] = src[0];
                dst[1] = src[1];
            }
            // ---- A tile: tap-shifted x row -> [w][c] fp16, zero pad ----
            {
                int dw = (br < 2)  ? ((k - 2) << br)       : 0;
                int dh = (br >= 2) ? ((k - 2) << (br - 2)) : 0;
                int hh = h + dh, ws = w + dw;
                bool ok = ((unsigned)hh < HH) && ((unsigned)ws < WW);
                const float* src = xn + ((size_t)(cc * 64 + ch * 32)) * HW + hh * WW + ws;
                __half2* dst = (__half2*)(sA + w * ASTR + ch * 32);
#pragma unroll
                for (int j = 0; j < 16; j++) {
                    float lo = ok ? __ldg(src + (2 * j) * HW)     : 0.f;
                    float hi = ok ? __ldg(src + (2 * j + 1) * HW) : 0.f;
                    dst[j] = __floats2half2_rn(lo, hi);
                }
            }
            __syncthreads();

            // ---- 4 K-steps of 16 over this 64-chunk ----
#pragma unroll
            for (int ks = 0; ks < 4; ks++) {
                uint32_t a[2][4];
#pragma unroll
                for (int mi = 0; mi < 2; mi++) {
                    uint32_t ad = aB + (uint32_t)(((m0 + mi * 16 + rOff) * ASTR +
                                                   ks * 16 + cOff) * 2);
                    ldsm_x4(a[mi][0], a[mi][1], a[mi][2], a[mi][3], ad);
                }
                uint32_t b[2][4];
#pragma unroll
                for (int nh = 0; nh < 2; nh++) {
                    uint32_t bd = bB + (uint32_t)(((ks * 16 + rOff) * ASTR +
                                                   n0 + nh * 16 + cOff) * 2);
                    ldsm_x4t(b[nh][0], b[nh][1], b[nh][2], b[nh][3], bd);
                }
#pragma unroll
                for (int mi = 0; mi < 2; mi++)
#pragma unroll
                    for (int ni = 0; ni < 4; ni++)
                        mma16816(acc[mi][ni], a[mi],
                                 b[ni >> 1][(ni & 1) * 2], b[ni >> 1][(ni & 1) * 2 + 1]);
            }
        }
    }

    // ---- epilogue: bias + scattered stores ----
    const float* bp = (br == 0) ? b1 : (br == 1) ? b2 : (br == 2) ? b3 : b4;
    const int g = lane >> 2, tig = lane & 3;
    float* ob = out + (((size_t)n * 256 + br * 64) * HH + h) * WW;
#pragma unroll
    for (int mi = 0; mi < 2; mi++) {
        int wr = m0 + mi * 16 + g;
#pragma unroll
        for (int ni = 0; ni < 4; ni++) {
            int co = n0 + ni * 8 + tig * 2;
            float bi0 = __ldg(bp + co), bi1 = __ldg(bp + co + 1);
            ob[(size_t)co * HW + wr]            = acc[mi][ni][0] + bi0;
            ob[(size_t)(co + 1) * HW + wr]      = acc[mi][ni][1] + bi1;
            ob[(size_t)co * HW + wr + 8]        = acc[mi][ni][2] + bi0;
            ob[(size_t)(co + 1) * HW + wr + 8]  = acc[mi][ni][3] + bi1;
        }
    }
}

extern "C" void kernel_launch(void* const* d_in, const int* in_sizes, int n_in,
                              void* d_out, int out_size) {
    const float* x  = (const float*)d_in[0];
    const float* w1 = (const float*)d_in[1];
    const float* b1 = (const float*)d_in[2];
    const float* w2 = (const float*)d_in[3];
    const float* b2 = (const float*)d_in[4];
    const float* w3 = (const float*)d_in[5];
    const float* b3 = (const float*)d_in[6];
    const float* w4 = (const float*)d_in[7];
    const float* b4 = (const float*)d_in[8];

    binarize_kernel<<<(4 * 5 * 256 * 64 + 255) / 256, 256>>>(w1, w2, w3, w4);

    dim3 grid(4, HH, NB);   // branch fastest: same-(n,h) CTAs adjacent -> L2 reuse of x
    mrb_mma<<<grid, 256>>>(x, b1, b2, b3, b4, (float*)d_out);
}

// round 13
// speedup vs baseline: 5.4509x; 1.0683x over previous
#include <cuda_runtime.h>
#include <cuda_fp16.h>
#include <cstdint>

#define CI 256
#define HH 128
#define WW 128
#define NB 16
#define HW (HH*WW)

// Binarized fp16 weights, layout [br][k][c][co]  (co contiguous, 64 per row)
__device__ __align__(16) __half g_wh[4 * 5 * 256 * 64];

__global__ void binarize_kernel(const float* __restrict__ w1, const float* __restrict__ w2,
                                const float* __restrict__ w3, const float* __restrict__ w4) {
    int idx = blockIdx.x * blockDim.x + threadIdx.x;
    if (idx >= 4 * 5 * 256 * 64) return;
    int co = idx & 63;
    int c  = (idx >> 6) & 255;
    int kk = idx >> 14;          // br*5 + k
    int k  = kk % 5;
    int br = kk / 5;
    const float* wp = (br == 0) ? w1 : (br == 1) ? w2 : (br == 2) ? w3 : w4;
    float v = wp[(co * CI + c) * 5 + k];
    g_wh[idx] = __float2half((v < 0.f) ? -1.f : 1.f);
}

__device__ __forceinline__ uint32_t smem_u32(const void* p) {
    return (uint32_t)__cvta_generic_to_shared(p);
}
__device__ __forceinline__ uint32_t h2_bits(__half2 h) {
    union { __half2 h; uint32_t u; } cvt;
    cvt.h = h;
    return cvt.u;
}
// 128B rows + XOR-16B swizzle: STS.128 and ldmatrix both conflict-free
__device__ __forceinline__ uint32_t swz(uint32_t row, uint32_t colByte) {
    return row * 128 + (colByte ^ ((row & 7) << 4));
}
__device__ __forceinline__ void ldsm_x4(uint32_t& r0, uint32_t& r1, uint32_t& r2, uint32_t& r3,
                                        uint32_t a) {
    asm volatile("ldmatrix.sync.aligned.m8n8.x4.shared.b16 {%0,%1,%2,%3}, [%4];"
                 : "=r"(r0), "=r"(r1), "=r"(r2), "=r"(r3) : "r"(a));
}
__device__ __forceinline__ void ldsm_x4t(uint32_t& r0, uint32_t& r1, uint32_t& r2, uint32_t& r3,
                                         uint32_t a) {
    asm volatile("ldmatrix.sync.aligned.m8n8.x4.trans.shared.b16 {%0,%1,%2,%3}, [%4];"
                 : "=r"(r0), "=r"(r1), "=r"(r2), "=r"(r3) : "r"(a));
}
__device__ __forceinline__ void mma16816(float* c, const uint32_t* a, uint32_t b0, uint32_t b1) {
    asm volatile(
        "mma.sync.aligned.m16n8k16.row.col.f32.f16.f16.f32 "
        "{%0,%1,%2,%3}, {%4,%5,%6,%7}, {%8,%9}, {%0,%1,%2,%3};"
        : "+f"(c[0]), "+f"(c[1]), "+f"(c[2]), "+f"(c[3])
        : "r"(a[0]), "r"(a[1]), "r"(a[2]), "r"(a[3]), "r"(b0), "r"(b1));
}

// ---------- main: one CTA = (branch, n, h); GEMM 128x64 x K1280 via HMMA ----------
__global__ __launch_bounds__(256) void mrb_mma(
    const float* __restrict__ x,
    const float* __restrict__ b1, const float* __restrict__ b2,
    const float* __restrict__ b3, const float* __restrict__ b4,
    float* __restrict__ out) {

    // A: 136 rows (w+4, covers w-halo -4..131) x 64 c halves (128B swizzled rows)
    __shared__ __align__(1024) __half sA[136 * 64];
    // B: 64 rows (c) x 64 co halves
    __shared__ __align__(1024) __half sB[64 * 64];

    const int br = blockIdx.x;
    const int h  = blockIdx.y;
    const int n  = blockIdx.z;
    const int tid = threadIdx.x, wid = tid >> 5, lane = tid & 31;
    const bool horiz = (br < 2);

    const uint32_t aB = smem_u32(sA);
    const uint32_t bB = smem_u32(sB);

    // MMA warps 0-3, each a 64m x 32n tile
    const int m0 = (wid & 1) * 64;
    const int n0 = (wid >> 1) * 32;
    const int rOff = (lane & 7) + (((lane >> 3) & 1) << 3);
    const int cOff = (lane >> 4) << 3;

    float acc[4][4][4];
#pragma unroll
    for (int mi = 0; mi < 4; mi++)
#pragma unroll
        for (int ni = 0; ni < 4; ni++)
#pragma unroll
            for (int r = 0; r < 4; r++) acc[mi][ni][r] = 0.f;

    const float* xn = x + (size_t)n * CI * HW;
    const int w  = tid & 127;
    const int ch = tid >> 7;   // which 32-c half of the 64-chunk

    // stage one [row][32c] strip: 8 LDG + pack -> 1 STS.128, x4
    auto stage_row = [&](int row, int chh, int ws, int hh, int cc) {
        bool ok = ((unsigned)hh < HH) && ((unsigned)ws < WW);
        const float* src = xn + (size_t)(cc * 64 + chh * 32) * HW + hh * WW + ws;
#pragma unroll
        for (int j = 0; j < 4; j++) {
            float f[8];
#pragma unroll
            for (int t = 0; t < 8; t++)
                f[t] = ok ? __ldg(src + (size_t)(j * 8 + t) * HW) : 0.f;
            uint4 v;
            v.x = h2_bits(__floats2half2_rn(f[0], f[1]));
            v.y = h2_bits(__floats2half2_rn(f[2], f[3]));
            v.z = h2_bits(__floats2half2_rn(f[4], f[5]));
            v.w = h2_bits(__floats2half2_rn(f[6], f[7]));
            *(uint4*)((char*)sA + swz(row, chh * 64 + j * 16)) = v;
        }
    };

    for (int cc = 0; cc < 4; cc++) {
        __syncthreads();
        if (horiz) {
            // stage halo A once per c-chunk: rows 0..135 <-> ws = -4..131
            stage_row(w, ch, w - 4, h, cc);
            if (tid < 16) stage_row(128 + (tid & 7), (tid >> 3) & 1, 124 + (tid & 7), h, cc);
        }
#pragma unroll 1
        for (int k = 0; k < 5; k++) {
            if (k) __syncthreads();
            // ---- B tile: 64 c-rows x 64 co ----
            {
                int c = tid & 63, seg = tid >> 6;
                const uint4* src = (const uint4*)(g_wh +
                    (((size_t)(br * 5 + k) * 256) + cc * 64 + c) * 64 + seg * 16);
                *(uint4*)((char*)sB + swz(c, seg * 32))      = src[0];
                *(uint4*)((char*)sB + swz(c, seg * 32 + 16)) = src[1];
            }
            // ---- vertical branches: restage A (different h row per tap) ----
            if (!horiz) {
                int dh = (k - 2) << (br - 2);
                stage_row(w + 4, ch, w, h + dh, cc);
            }
            __syncthreads();

            if (wid < 4) {
                const int dw = horiz ? ((k - 2) << br) : 0;
                const int rowBase = 4 + dw + m0;
#pragma unroll
                for (int ks = 0; ks < 4; ks++) {
                    uint32_t a[4][4];
#pragma unroll
                    for (int mi = 0; mi < 4; mi++) {
                        uint32_t ad = aB + swz(rowBase + mi * 16 + rOff,
                                               (uint32_t)(ks * 16 + cOff) * 2);
                        ldsm_x4(a[mi][0], a[mi][1], a[mi][2], a[mi][3], ad);
                    }
                    uint32_t b[2][4];
#pragma unroll
                    for (int nh = 0; nh < 2; nh++) {
                        uint32_t bd = bB + swz(ks * 16 + rOff,
                                               (uint32_t)(n0 + nh * 16 + cOff) * 2);
                        ldsm_x4t(b[nh][0], b[nh][1], b[nh][2], b[nh][3], bd);
                    }
#pragma unroll
                    for (int mi = 0; mi < 4; mi++)
#pragma unroll
                        for (int ni = 0; ni < 4; ni++)
                            mma16816(acc[mi][ni], a[mi],
                                     b[ni >> 1][(ni & 1) * 2], b[ni >> 1][(ni & 1) * 2 + 1]);
                }
            }
        }
    }

    // ---- epilogue: bias + stores (MMA warps only) ----
    if (wid < 4) {
        const float* bp = (br == 0) ? b1 : (br == 1) ? b2 : (br == 2) ? b3 : b4;
        const int g = lane >> 2, tig = lane & 3;
        float* ob = out + (((size_t)n * 256 + br * 64) * HH + h) * WW;
#pragma unroll
        for (int mi = 0; mi < 4; mi++) {
            int wr = m0 + mi * 16 + g;
#pragma unroll
            for (int ni = 0; ni < 4; ni++) {
                int co = n0 + ni * 8 + tig * 2;
                float bi0 = __ldg(bp + co), bi1 = __ldg(bp + co + 1);
                ob[(size_t)co * HW + wr]           = acc[mi][ni][0] + bi0;
                ob[(size_t)(co + 1) * HW + wr]     = acc[mi][ni][1] + bi1;
                ob[(size_t)co * HW + wr + 8]       = acc[mi][ni][2] + bi0;
                ob[(size_t)(co + 1) * HW + wr + 8] = acc[mi][ni][3] + bi1;
            }
        }
    }
}

extern "C" void kernel_launch(void* const* d_in, const int* in_sizes, int n_in,
                              void* d_out, int out_size) {
    const float* x  = (const float*)d_in[0];
    const float* w1 = (const float*)d_in[1];
    const float* b1 = (const float*)d_in[2];
    const float* w2 = (const float*)d_in[3];
    const float* b2 = (const float*)d_in[4];
    const float* w3 = (const float*)d_in[5];
    const float* b3 = (const float*)d_in[6];
    const float* w4 = (const float*)d_in[7];
    const float* b4 = (const float*)d_in[8];

    binarize_kernel<<<(4 * 5 * 256 * 64 + 255) / 256, 256>>>(w1, w2, w3, w4);

    dim3 grid(4, HH, NB);   // branch fastest: same-(n,h) CTAs adjacent -> L2 reuse of x
    mrb_mma<<<grid, 256>>>(x, b1, b2, b3, b4, (float*)d_out);
}

// round 16
// speedup vs baseline: 7.3308x; 1.3449x over previous
#include <cuda_runtime.h>
#include <cuda_fp16.h>
#include <cstdint>

#define CI 256
#define HH 128
#define WW 128
#define NB 16
#define HW (HH*WW)

// Sign bitmasks in MMA-fragment order:
// [br][ktap][cc][nhalf][lane][ni] : uint16, bit (ks*4 + j),
// j: 0->B[k0][n],1->B[k0+1][n],2->B[k0+8][n],3->B[k0+9][n]; k0=2*(lane%4), n=lane/4 (+ni*8+nhalf*32)
__device__ __align__(16) unsigned short g_bm[20480];

__global__ void sign_pack(const float* __restrict__ w1, const float* __restrict__ w2,
                          const float* __restrict__ w3, const float* __restrict__ w4) {
    int idx = blockIdx.x * blockDim.x + threadIdx.x;
    if (idx >= 20480) return;
    int ni   = idx & 3;
    int lane = (idx >> 2) & 31;
    int nh   = (idx >> 7) & 1;
    int cc   = (idx >> 8) & 3;
    int rest = idx >> 10;          // br*5 + kt
    int kt   = rest % 5;
    int br   = rest / 5;
    const float* wp = (br == 0) ? w1 : (br == 1) ? w2 : (br == 2) ? w3 : w4;
    int co  = nh * 32 + ni * 8 + (lane >> 2);
    int kk0 = (lane & 3) * 2;
    unsigned short v = 0;
    for (int ks = 0; ks < 4; ks++)
        for (int j = 0; j < 4; j++) {
            int c = cc * 64 + ks * 16 + kk0 + (j & 1) + ((j & 2) ? 8 : 0);
            if (wp[(co * CI + c) * 5 + kt] < 0.f) v |= (unsigned short)(1u << (ks * 4 + j));
        }
    g_bm[idx] = v;
}

__device__ __forceinline__ uint32_t smem_u32(const void* p) {
    return (uint32_t)__cvta_generic_to_shared(p);
}
__device__ __forceinline__ uint32_t h2_bits(__half2 h) {
    union { __half2 h; uint32_t u; } cvt; cvt.h = h; return cvt.u;
}
// 128B rows + XOR-16B swizzle: STS.128 and ldmatrix both conflict-free
__device__ __forceinline__ uint32_t swz(uint32_t row, uint32_t colByte) {
    return row * 128 + (colByte ^ ((row & 7) << 4));
}
__device__ __forceinline__ void ldsm_x4(uint32_t& r0, uint32_t& r1, uint32_t& r2, uint32_t& r3,
                                        uint32_t a) {
    asm volatile("ldmatrix.sync.aligned.m8n8.x4.shared.b16 {%0,%1,%2,%3}, [%4];"
                 : "=r"(r0), "=r"(r1), "=r"(r2), "=r"(r3) : "r"(a));
}
__device__ __forceinline__ void mma16816(float* c, const uint32_t* a, uint32_t b0, uint32_t b1) {
    asm volatile(
        "mma.sync.aligned.m16n8k16.row.col.f32.f16.f16.f32 "
        "{%0,%1,%2,%3}, {%4,%5,%6,%7}, {%8,%9}, {%0,%1,%2,%3};"
        : "+f"(c[0]), "+f"(c[1]), "+f"(c[2]), "+f"(c[3])
        : "r"(a[0]), "r"(a[1]), "r"(a[2]), "r"(a[3]), "r"(b0), "r"(b1));
}

#define HROWS 136              // horizontal halo tile rows (w = -4..131)
#define HSTRIDE (HROWS * 128)  // bytes per horiz buffer
#define VSTRIDE (128 * 128)    // bytes per vert buffer

__global__ __launch_bounds__(256, 2) void mrb_mma(
    const float* __restrict__ x,
    const float* __restrict__ b1, const float* __restrict__ b2,
    const float* __restrict__ b3, const float* __restrict__ b4,
    float* __restrict__ out) {

    __shared__ __align__(1024) __half sbuf[2 * HSTRIDE / 2];  // 34816 B

    const int br = blockIdx.x;
    const int h  = blockIdx.y;
    const int n  = blockIdx.z;
    const int tid = threadIdx.x, wid = tid >> 5, lane = tid & 31;
    const bool horiz = (br < 2);
    const bool consumer = (wid < 4);
    const int ptid = tid - 128;  // producer thread id (valid for wid>=4)

    const uint32_t sbase = smem_u32(sbuf);
    const float* xn = x + (size_t)n * CI * HW;

    // consumer tile geometry (64m x 32n per warp)
    const int m0 = (wid & 1) * 64;
    const int nh = (wid >> 1) & 1;
    const int n0 = nh * 32;
    const int rOff = (lane & 7) + (((lane >> 3) & 1) << 3);
    const int cOff = (lane >> 4) << 3;

    float acc[4][4][4];
#pragma unroll
    for (int mi = 0; mi < 4; mi++)
#pragma unroll
        for (int ni = 0; ni < 4; ni++)
#pragma unroll
            for (int r = 0; r < 4; r++) acc[mi][ni][r] = 0.f;

    // ---- producer helpers ----
    // stage one 32c strip of one row into buffer (horiz path, inline LDG->STS)
    auto stage_unit_h = [&](uint32_t bufB, int r, int chh, int cc) {
        int ws = r - 4;
        bool ok = (unsigned)ws < WW;
        const float* src = xn + (size_t)(cc * 64 + chh * 32) * HW + h * WW + ws;
#pragma unroll
        for (int j = 0; j < 4; j++) {
            float f[8];
#pragma unroll
            for (int t = 0; t < 8; t++)
                f[t] = ok ? __ldg(src + (size_t)(j * 8 + t) * HW) : 0.f;
            uint4 v;
            v.x = h2_bits(__floats2half2_rn(f[0], f[1]));
            v.y = h2_bits(__floats2half2_rn(f[2], f[3]));
            v.z = h2_bits(__floats2half2_rn(f[4], f[5]));
            v.w = h2_bits(__floats2half2_rn(f[6], f[7]));
            *(uint4*)((char*)sbuf + (bufB - sbase) + swz(r, chh * 64 + j * 16)) = v;
        }
    };

    // ---- consumer tap: MMA over one staged buffer ----
    auto consume_tap = [&](uint32_t bufB, int rowBase, int kt, int cc) {
        const ushort4* bmp = (const ushort4*)(g_bm +
            ((((br * 5 + kt) * 4 + cc) * 2 + nh) * 32 + lane) * 4);
        ushort4 e = *bmp;
        unsigned ev[4] = {e.x, e.y, e.z, e.w};
#pragma unroll
        for (int ks = 0; ks < 4; ks++) {
            uint32_t a[4][4];
#pragma unroll
            for (int mi = 0; mi < 4; mi++) {
                uint32_t ad = bufB + swz(rowBase + mi * 16 + rOff,
                                         (uint32_t)(ks * 16 + cOff) * 2);
                ldsm_x4(a[mi][0], a[mi][1], a[mi][2], a[mi][3], ad);
            }
#pragma unroll
            for (int ni = 0; ni < 4; ni++) {
                unsigned bits = (ev[ni] >> (ks * 4)) & 0xFu;
                uint32_t bb0 = 0x3C003C00u | ((bits & 1u) << 15) | ((bits & 2u) << 30);
                uint32_t bb1 = 0x3C003C00u | (((bits >> 2) & 1u) << 15) | ((bits & 8u) << 28);
#pragma unroll
                for (int mi = 0; mi < 4; mi++)
                    mma16816(acc[mi][ni], a[mi], bb0, bb1);
            }
        }
    };

    if (horiz) {
        // ---------- horizontal: halo tile per c-chunk, 1 barrier per chunk ----------
        if (!consumer) {
            for (int u = ptid; u < 272; u += 128)
                stage_unit_h(sbase, u >> 1, u & 1, 0);
        }
        __syncthreads();
        for (int cc = 0; cc < 4; cc++) {
            uint32_t bufB = sbase + (cc & 1) * HSTRIDE;
            if (consumer) {
#pragma unroll 1
                for (int k = 0; k < 5; k++) {
                    int dw = (k - 2) << br;
                    consume_tap(bufB, 4 + dw + m0, k, cc);
                }
            } else if (cc < 3) {
                uint32_t nb = sbase + ((cc + 1) & 1) * HSTRIDE;
                for (int u = ptid; u < 272; u += 128)
                    stage_unit_h(nb, u >> 1, u & 1, cc + 1);
            }
            __syncthreads();
        }
    } else {
        // ---------- vertical: per-tap 128x64 tile, reg-pipelined producers ----------
        float rg[2][32];
        // producer LDG for step s -> regs
        auto vload = [&](int s) {
            int cc = s / 5, k = s % 5;
            int dh = (k - 2) << (br - 2);
            int hh = h + dh;
            bool ok = (unsigned)hh < HH;
            const float* src = xn + (size_t)(cc * 64) * HW + hh * WW + ptid;
#pragma unroll
            for (int i = 0; i < 2; i++)
#pragma unroll
                for (int t = 0; t < 32; t++)
                    rg[i][t] = ok ? __ldg(src + (size_t)(i * 32 + t) * HW) : 0.f;
        };
        auto vsts = [&](uint32_t bufB) {
#pragma unroll
            for (int i = 0; i < 2; i++)
#pragma unroll
                for (int j = 0; j < 4; j++) {
                    uint4 v;
                    v.x = h2_bits(__floats2half2_rn(rg[i][j * 8 + 0], rg[i][j * 8 + 1]));
                    v.y = h2_bits(__floats2half2_rn(rg[i][j * 8 + 2], rg[i][j * 8 + 3]));
                    v.z = h2_bits(__floats2half2_rn(rg[i][j * 8 + 4], rg[i][j * 8 + 5]));
                    v.w = h2_bits(__floats2half2_rn(rg[i][j * 8 + 6], rg[i][j * 8 + 7]));
                    *(uint4*)((char*)sbuf + (bufB - sbase) + swz(ptid, i * 64 + j * 16)) = v;
                }
        };

        if (!consumer) {
            vload(0);
            vsts(sbase);          // step 0 -> buf0
            vload(1);             // step 1 held in regs
        }
        __syncthreads();
#pragma unroll 1
        for (int s = 0; s < 20; s++) {
            if (consumer) {
                consume_tap(sbase + (s & 1) * VSTRIDE, m0, s % 5, s / 5);
            } else {
                if (s < 19) vsts(sbase + ((s + 1) & 1) * VSTRIDE);
                if (s < 18) vload(s + 2);
            }
            __syncthreads();
        }
    }

    // ---- epilogue: bias + stores (consumers only) ----
    if (consumer) {
        const float* bp = (br == 0) ? b1 : (br == 1) ? b2 : (br == 2) ? b3 : b4;
        const int g = lane >> 2, tig = lane & 3;
        float* ob = out + (((size_t)n * 256 + br * 64) * HH + h) * WW;
#pragma unroll
        for (int mi = 0; mi < 4; mi++) {
            int wr = m0 + mi * 16 + g;
#pragma unroll
            for (int ni = 0; ni < 4; ni++) {
                int co = n0 + ni * 8 + tig * 2;
                float bi0 = __ldg(bp + co), bi1 = __ldg(bp + co + 1);
                ob[(size_t)co * HW + wr]           = acc[mi][ni][0] + bi0;
                ob[(size_t)(co + 1) * HW + wr]     = acc[mi][ni][1] + bi1;
                ob[(size_t)co * HW + wr + 8]       = acc[mi][ni][2] + bi0;
                ob[(size_t)(co + 1) * HW + wr + 8] = acc[mi][ni][3] + bi1;
            }
        }
    }
}

extern "C" void kernel_launch(void* const* d_in, const int* in_sizes, int n_in,
                              void* d_out, int out_size) {
    const float* x  = (const float*)d_in[0];
    const float* w1 = (const float*)d_in[1];
    const float* b1 = (const float*)d_in[2];
    const float* w2 = (const float*)d_in[3];
    const float* b2 = (const float*)d_in[4];
    const float* w3 = (const float*)d_in[5];
    const float* b3 = (const float*)d_in[6];
    const float* w4 = (const float*)d_in[7];
    const float* b4 = (const float*)d_in[8];

    sign_pack<<<(20480 + 255) / 256, 256>>>(w1, w2, w3, w4);

    dim3 grid(4, HH, NB);
    mrb_mma<<<grid, 256>>>(x, b1, b2, b3, b4, (float*)d_out);
}